// round 16
// baseline (speedup 1.0000x reference)
#include <cuda_runtime.h>
#include <math.h>

#define A_NUM 15
#define NUM_FG 128
#define RPN_BATCH_C 256
#define MAX_G 512
#define MAX_B 512
#define TPB 512
#define NW (TPB / 32)

// Base anchors in constant memory (runtime-indexed)
__constant__ float c_base[60] = {
    -3.5f,   2.f,  18.5f,  13.f,   -15.f,   -4.f,  30.f,   19.f,
   -38.f,  -16.f,  53.f,   31.f,   -84.f,  -40.f,  99.f,   55.f,
  -176.f,  -88.f, 191.f,  103.f,     0.f,    0.f,  15.f,   15.f,
    -8.f,   -8.f,  23.f,   23.f,   -24.f,  -24.f,  39.f,   39.f,
   -56.f,  -56.f,  71.f,   71.f,  -120.f, -120.f, 135.f,  135.f,
     2.5f,  -3.f,  12.5f,  18.f,    -3.f,  -14.f,  18.f,   29.f,
   -14.f,  -36.f,  29.f,   51.f,   -36.f,  -80.f,  51.f,   95.f,
   -80.f, -168.f,  95.f,  183.f
};

__device__ int g_bp[MAX_B];
__device__ int g_bn[MAX_B];
__device__ unsigned long long g_pack[MAX_G];   // (iou_bits<<32)|~k ; 0 = untouched
__device__ int g_kfirst = 0x7fffffff;          // first inside anchor (global)
__device__ unsigned g_bar_count = 0;
__device__ volatile unsigned g_bar_gen = 0;

// Software grid barrier. Valid: all blocks co-resident (grid = 2 * #SMs, occ 2).
__device__ __forceinline__ void grid_barrier(int nblocks) {
    __syncthreads();
    if (threadIdx.x == 0) {
        __threadfence();
        unsigned gen = g_bar_gen;
        if (atomicAdd(&g_bar_count, 1u) == (unsigned)(nblocks - 1)) {
            atomicExch(&g_bar_count, 0u);
            __threadfence();
            g_bar_gen = gen + 1;
        } else {
            while (g_bar_gen == gen) { }
        }
        __threadfence();
    }
    __syncthreads();
}

__global__ void __launch_bounds__(TPB, 2)
k_fused(const float* __restrict__ gt, const float* __restrict__ meta,
        float* __restrict__ out, int K, int r, int c, int G,
        int nblocks, int chunk, float inv_c) {
    __shared__ float4 s_gt[MAX_G];
    __shared__ float  s_area[MAX_G];
    __shared__ int    s_wp[NW], s_wn[NW];
    __shared__ int    s_sp[MAX_B], s_sn[MAX_B];

    const int tid  = threadIdx.x;
    const int bid  = blockIdx.x;
    const int lane = tid & 31;
    const int warp = tid >> 5;
    const unsigned FULL = 0xffffffffu;

    for (int g = tid; g < G; g += TPB) {
        float4 b = reinterpret_cast<const float4*>(gt)[g];
        s_gt[g] = b;
        s_area[g] = (b.z - b.x + 1.0f) * (b.w - b.y + 1.0f);
    }
    __syncthreads();

    const float h = meta[0], w = meta[1];
    const float wm1 = w - 1.f, hm1 = h - 1.f;
    float*  lab = out + (size_t)8 * K;
    float4* tgt = reinterpret_cast<float4*>(out + (size_t)4 * K);

    const int base = bid * chunk;
    const int end  = min(base + chunk, K);
    const float4 gb0 = s_gt[0];

    // ============ Phase 1 (single pass: chunk <= TPB) =====================
    for (int sb = base; sb < end; sb += TPB) {
        int k = sb + tid;
        int kk = min(k, end - 1);
        // kk/15 and t2/c via verified float-reciprocal (no int division)
        int t2 = (int)(((float)kk + 0.5f) * (1.0f / 15.0f));
        int a  = kk - t2 * A_NUM;
        int ii = (int)(((float)t2 + 0.5f) * inv_c);
        int jj = t2 - ii * c;
        float sx = (float)(jj << 4);
        float sy = (float)(ii << 4);

        // per-warp spatial window
        float sxlo = sx, sxhi = sx, sylo = sy, syhi = sy;
        #pragma unroll
        for (int off = 16; off; off >>= 1) {
            sxlo = fminf(sxlo, __shfl_xor_sync(FULL, sxlo, off));
            sxhi = fmaxf(sxhi, __shfl_xor_sync(FULL, sxhi, off));
            sylo = fminf(sylo, __shfl_xor_sync(FULL, sylo, off));
            syhi = fmaxf(syhi, __shfl_xor_sync(FULL, syhi, off));
        }
        float xlo = sxlo - 178.f, xhi = sxhi + 193.f;
        float ylo = sylo - 170.f, yhi = syhi + 185.f;

        float x1 = sx + c_base[a * 4 + 0];
        float y1 = sy + c_base[a * 4 + 1];
        float x2 = sx + c_base[a * 4 + 2];
        float y2 = sy + c_base[a * 4 + 3];

        bool valid  = (k < end);
        bool inside = (x1 >= 0.f) && (y1 >= 0.f) && (x2 < w) && (y2 < h);
        bool need   = inside && valid;

        if (valid)
            reinterpret_cast<float4*>(out)[k] = make_float4(x1, y1, x2, y2);

        // global first-inside-anchor (one RED per warp-pass)
        {
            unsigned im = __ballot_sync(FULL, need);
            if (im && lane == (unsigned)(__ffs(im) - 1))
                atomicMin(&g_kfirst, k);
        }

        // inside anchors are unclipped; clip is identity here
        float cx1 = fminf(fmaxf(x1, 0.f), wm1);
        float cy1 = fminf(fmaxf(y1, 0.f), hm1);
        float cx2 = fminf(fmaxf(x2, 0.f), wm1);
        float cy2 = fminf(fmaxf(y2, 0.f), hm1);
        float areaA = (cx2 - cx1 + 1.f) * (cy2 - cy1 + 1.f);

        float bi = 0.f, bd = 1.f;     // matches "all-zero row -> argmax 0"
        int   bg = -1;

        if (__any_sync(FULL, need)) {
            for (int gbs = 0; gbs < G; gbs += 32) {
                int g = gbs + lane;
                bool ok = false;
                if (g < G) {
                    float4 b = s_gt[g];
                    ok = (b.y <= yhi) && (b.w >= ylo) && (b.x <= xhi) && (b.z >= xlo);
                }
                unsigned m = __ballot_sync(FULL, ok);
                while (m) {
                    int src = __ffs(m) - 1;
                    m &= m - 1;
                    int gc = gbs + src;
                    // uniform address -> broadcast LDS (conflict-free)
                    float4 bb = s_gt[gc];
                    float  ba = s_area[gc];
                    float iw = (fminf(cx2, bb.z) - fmaxf(cx1, bb.x)) + 1.f;
                    float ih = (fminf(cy2, bb.w) - fmaxf(cy1, bb.y)) + 1.f;
                    float inter = fmaxf(iw, 0.f) * fmaxf(ih, 0.f);
                    float denom = (areaA + ba) - inter;
                    // per-anchor running max (cross-multiplication, exact)
                    if (inter * bd > bi * denom) {
                        bi = inter; bd = denom; bg = gc;
                    }
                }
            }
        }

        if (valid) {
            if (!inside) {
                tgt[k] = make_float4(0.f, 0.f, 0.f, 0.f);
                lab[k] = -1.f;
            } else {
                float mo = __fdiv_rn(bi, bd);   // exact: feeds label thresholds
                float l = -1.f;
                if (mo < 0.3f)  l = 0.f;
                if (mo >= 0.7f) l = 1.f;
                lab[k] = l;

                float4 gb = (bg >= 0) ? s_gt[bg] : gb0;
                float ew = cx2 - cx1 + 1.f, eh = cy2 - cy1 + 1.f;
                float ecx = cx1 + 0.5f * ew, ecy = cy1 + 0.5f * eh;
                float gw = gb.z - gb.x + 1.f, gh = gb.w - gb.y + 1.f;
                float gcx = gb.x + 0.5f * gw, gcy = gb.y + 0.5f * gh;
                tgt[k] = make_float4(__fdividef(gcx - ecx, ew),
                                     __fdividef(gcy - ecy, eh),
                                     __logf(__fdividef(gw, ew)),
                                     __logf(__fdividef(gh, eh)));
            }
        }
    }

    // ============ Phase 2: (gt, shape) warp-tasks =========================
    // Each warp handles one (gt, shape) pair over the shape-exact window
    // (superset window + strict in-body guards -> exact; validated in R13).
    for (int task = bid * NW + warp; task < G * A_NUM; task += nblocks * NW) {
        int g = task / A_NUM;
        int a = task - g * A_NUM;
        float4 b = s_gt[g];
        float areaB = s_area[g];
        float bax1 = c_base[a * 4 + 0];
        float bay1 = c_base[a * 4 + 1];
        float bax2 = c_base[a * 4 + 2];
        float bay2 = c_base[a * 4 + 3];
        float areaA = (bax2 - bax1 + 1.f) * (bay2 - bay1 + 1.f);   // exact

        float sxmin = fmaxf(-bax1, b.x - bax2 - 1.f);
        float sxmax = fminf(w - bax2, b.z - bax1 + 1.f);
        float symin = fmaxf(-bay1, b.y - bay2 - 1.f);
        float symax = fminf(h - bay2, b.w - bay1 + 1.f);
        int j0 = max(0, (int)ceilf(sxmin * 0.0625f));
        int j1 = min(c - 1, (int)floorf(sxmax * 0.0625f));
        int i0 = max(0, (int)ceilf(symin * 0.0625f));
        int i1 = min(r - 1, (int)floorf(symax * 0.0625f));
        int nx = j1 - j0 + 1;
        int ny = i1 - i0 + 1;
        if (nx <= 0 || ny <= 0) continue;
        int ncell = nx * ny;
        float inv_nx = 1.0f / (float)nx;

        float bi = 0.f, bd = 1.f;
        int   bk = 0x7fffffff;

        for (int t = lane; t < ncell; t += 32) {
            int dv = (int)(((float)t + 0.5f) * inv_nx);
            int jj = j0 + (t - dv * nx);
            int ii = i0 + dv;
            float sx = (float)(jj << 4);
            float sy = (float)(ii << 4);
            float x1 = sx + bax1;
            float y1 = sy + bay1;
            float x2 = sx + bax2;
            float y2 = sy + bay2;
            bool ins = (x1 >= 0.f) && (y1 >= 0.f) && (x2 < w) && (y2 < h);
            float iw = (fminf(x2, b.z) - fmaxf(x1, b.x)) + 1.f;
            float ih = (fminf(y2, b.w) - fmaxf(y1, b.y)) + 1.f;
            float inter = fmaxf(iw, 0.f) * fmaxf(ih, 0.f);
            float denom = (areaA + areaB) - inter;
            int k = (ii * c + jj) * A_NUM + a;
            float p1 = inter * bd, p2 = bi * denom;
            // bi starts at 0 -> only inter>0 can be taken; exact tie -> min k
            if (ins && (p1 > p2 || (p1 == p2 && bi > 0.f && k < bk))) {
                bi = inter; bd = denom; bk = k;
            }
        }

        #pragma unroll
        for (int off = 16; off; off >>= 1) {
            float oi = __shfl_down_sync(FULL, bi, off);
            float od = __shfl_down_sync(FULL, bd, off);
            int   ok = __shfl_down_sync(FULL, bk, off);
            float p1 = oi * bd, p2 = bi * od;
            if (p1 > p2 || (p1 == p2 && oi > 0.f && ok < bk)) {
                bi = oi; bd = od; bk = ok;
            }
        }
        if (lane == 0 && bi > 0.f) {
            float iou = __fdiv_rn(bi, bd);       // one division per task
            unsigned long long pk =
                ((unsigned long long)__float_as_uint(iou) << 32)
                | (unsigned)(~bk);
            atomicMax(&g_pack[g], pk);           // RED, ~15 tasks/gt total
        }
    }

    grid_barrier(nblocks);

    // ---- apply per-gt winners falling in my chunk, then count ------------
    {
        int kfirst = __ldcg(&g_kfirst);
        if (tid < G) {
            unsigned long long pk = __ldcg(&g_pack[tid]);
            int kw = (pk == 0ull) ? kfirst
                                  : (int)(~(unsigned)(pk & 0xffffffffull));
            if (kw >= base && kw < end) lab[kw] = 1.0f;
        }
    }
    __syncthreads();

    int cp = 0, cn = 0;
    for (int k = base + tid; k < end; k += TPB) {
        float l = lab[k];               // all writes here were by this block
        cp += (l == 1.f);
        cn += (l == 0.f);
    }
    #pragma unroll
    for (int off = 16; off; off >>= 1) {
        cp += __shfl_down_sync(FULL, cp, off);
        cn += __shfl_down_sync(FULL, cn, off);
    }
    if (lane == 0) { s_wp[warp] = cp; s_wn[warp] = cn; }
    __syncthreads();
    if (tid == 0) {
        int p = 0, n = 0;
        #pragma unroll
        for (int v = 0; v < NW; v++) { p += s_wp[v]; n += s_wn[v]; }
        g_bp[bid] = p; g_bn[bid] = n;
    }

    grid_barrier(nblocks);

    // ---- reset persistent state for next graph replay (post-read) --------
    if (bid == 0) {
        if (tid < G) g_pack[tid] = 0ull;
        if (tid == 0) g_kfirst = 0x7fffffff;
    }

    // ---- shfl-based scan of block counts + apply subsampling -------------
    int vp = (tid < nblocks) ? __ldcg(&g_bp[tid]) : 0;
    int vn = (tid < nblocks) ? __ldcg(&g_bn[tid]) : 0;
    #pragma unroll
    for (int off = 1; off < 32; off <<= 1) {
        int tp = __shfl_up_sync(FULL, vp, off);
        int tn = __shfl_up_sync(FULL, vn, off);
        if (lane >= off) { vp += tp; vn += tn; }
    }
    if (lane == 31) { s_wp[warp] = vp; s_wn[warp] = vn; }
    __syncthreads();
    if (warp == 0 && lane < NW) {
        int wv = s_wp[lane], wn2 = s_wn[lane];
        #pragma unroll
        for (int off = 1; off < NW; off <<= 1) {
            int tp = __shfl_up_sync(0xffffu, wv, off);
            int tn = __shfl_up_sync(0xffffu, wn2, off);
            if (lane >= off) { wv += tp; wn2 += tn; }
        }
        s_wp[lane] = wv; s_wn[lane] = wn2;
    }
    __syncthreads();
    if (warp > 0) { vp += s_wp[warp - 1]; vn += s_wn[warp - 1]; }
    s_sp[tid] = vp; s_sn[tid] = vn;
    __syncthreads();

    int runP = (bid > 0) ? s_sp[bid - 1] : 0;
    int runN = (bid > 0) ? s_sn[bid - 1] : 0;
    int totP = s_sp[nblocks - 1];
    const int numBg = RPN_BATCH_C - (totP < NUM_FG ? totP : NUM_FG);
    __syncthreads();

    for (int s = base; s < end; s += TPB) {
        int k = s + tid;
        float l = (k < end) ? lab[k] : -1.f;
        int pos = (l == 1.f);
        int neg = (l == 0.f);
        unsigned ballp = __ballot_sync(FULL, pos);
        unsigned balln = __ballot_sync(FULL, neg);
        if (lane == 0) { s_wp[warp] = __popc(ballp); s_wn[warp] = __popc(balln); }
        __syncthreads();
        int wp = 0, wn = 0, totPb = 0, totNb = 0;
        #pragma unroll
        for (int v = 0; v < NW; v++) {
            int a2 = s_wp[v], b2 = s_wn[v];
            if (v < warp) { wp += a2; wn += b2; }
            totPb += a2; totNb += b2;
        }
        unsigned lm = (1u << lane) - 1u;
        int rp = runP + wp + __popc(ballp & lm) + 1;
        int rn = runN + wn + __popc(balln & lm) + 1;
        if (k < end) {
            if (pos && rp > NUM_FG) lab[k] = -1.f;
            if (neg && rn > numBg)  lab[k] = -1.f;
        }
        runP += totPb; runN += totNb;
        __syncthreads();
    }
}

// ---------------------------------------------------------------------------
extern "C" void kernel_launch(void* const* d_in, const int* in_sizes, int n_in,
                              void* d_out, int out_size) {
    const float* gt   = (const float*)d_in[0];
    const float* meta = (const float*)d_in[1];
    float* out = (float*)d_out;

    int G = in_sizes[0] / 4;
    if (G > MAX_G) G = MAX_G;
    int K  = in_sizes[2];
    int rc = K / A_NUM;
    int c  = (int)(sqrt((double)rc) + 0.5);
    int r  = rc / c;
    float inv_c = (float)(1.0 / (double)c);

    int dev = 0;
    cudaGetDevice(&dev);
    int nsm = 0;
    cudaDeviceGetAttribute(&nsm, cudaDevAttrMultiProcessorCount, dev);
    if (nsm <= 0) nsm = 148;
    int nblocks = 2 * nsm;               // 2 co-resident blocks per SM
    if (nblocks > MAX_B) nblocks = MAX_B;
    int chunk = (K + nblocks - 1) / nblocks;   // 494 for K=150000 -> 1 pass

    k_fused<<<nblocks, TPB>>>(gt, meta, out, K, r, c, G, nblocks, chunk, inv_c);
}

// round 17
// speedup vs baseline: 1.5109x; 1.5109x over previous
#include <cuda_runtime.h>
#include <math.h>

#define A_NUM 15
#define NUM_FG 128
#define RPN_BATCH_C 256
#define MAX_G 512
#define MAX_B 512
#define TPB 512
#define NW (TPB / 32)

// Base anchors in constant memory (runtime-indexed)
__constant__ float c_base[60] = {
    -3.5f,   2.f,  18.5f,  13.f,   -15.f,   -4.f,  30.f,   19.f,
   -38.f,  -16.f,  53.f,   31.f,   -84.f,  -40.f,  99.f,   55.f,
  -176.f,  -88.f, 191.f,  103.f,     0.f,    0.f,  15.f,   15.f,
    -8.f,   -8.f,  23.f,   23.f,   -24.f,  -24.f,  39.f,   39.f,
   -56.f,  -56.f,  71.f,   71.f,  -120.f, -120.f, 135.f,  135.f,
     2.5f,  -3.f,  12.5f,  18.f,    -3.f,  -14.f,  18.f,   29.f,
   -14.f,  -36.f,  29.f,   51.f,   -36.f,  -80.f,  51.f,   95.f,
   -80.f, -168.f,  95.f,  183.f
};

__device__ int g_bp[MAX_B];
__device__ int g_bn[MAX_B];
__device__ unsigned long long g_pack[MAX_G];   // (iou_bits<<32)|~k ; 0 = untouched
__device__ int g_kfirst = 0;                   // first inside anchor (analytic)
__device__ unsigned g_bar_count = 0;
__device__ volatile unsigned g_bar_gen = 0;

// Software grid barrier. Valid: all blocks co-resident (grid = 2 * #SMs, occ 2).
__device__ __forceinline__ void grid_barrier(int nblocks) {
    __syncthreads();
    if (threadIdx.x == 0) {
        __threadfence();
        unsigned gen = g_bar_gen;
        if (atomicAdd(&g_bar_count, 1u) == (unsigned)(nblocks - 1)) {
            atomicExch(&g_bar_count, 0u);
            __threadfence();
            g_bar_gen = gen + 1;
        } else {
            while (g_bar_gen == gen) { }
        }
        __threadfence();
    }
    __syncthreads();
}

__global__ void __launch_bounds__(TPB, 2)
k_fused(const float* __restrict__ gt, const float* __restrict__ meta,
        float* __restrict__ out, int K, int r, int c, int G,
        int nblocks, int chunk, float inv_c) {
    __shared__ float4 s_gt[MAX_G];
    __shared__ float  s_area[MAX_G];
    __shared__ int    s_wp[NW], s_wn[NW];
    __shared__ int    s_sp[MAX_B], s_sn[MAX_B];

    const int tid  = threadIdx.x;
    const int bid  = blockIdx.x;
    const int lane = tid & 31;
    const int warp = tid >> 5;
    const unsigned FULL = 0xffffffffu;

    for (int g = tid; g < G; g += TPB) {
        float4 b = reinterpret_cast<const float4*>(gt)[g];
        s_gt[g] = b;
        s_area[g] = (b.z - b.x + 1.0f) * (b.w - b.y + 1.0f);
    }
    __syncthreads();

    const float h = meta[0], w = meta[1];
    const float wm1 = w - 1.f, hm1 = h - 1.f;
    float*  lab = out + (size_t)8 * K;
    float4* tgt = reinterpret_cast<float4*>(out + (size_t)4 * K);

    const int base = bid * chunk;
    const int end  = min(base + chunk, K);
    const float4 gb0 = s_gt[0];

    // ---- analytic first-inside-anchor (no atomics; ordered by barrier) ---
    if (bid == 0 && tid == 0) {
        int kf = 0x7fffffff;
        #pragma unroll
        for (int a = 0; a < A_NUM; a++) {
            float bx1 = c_base[a * 4 + 0], by1 = c_base[a * 4 + 1];
            float bx2 = c_base[a * 4 + 2], by2 = c_base[a * 4 + 3];
            int ja = max(0, (int)ceilf(-bx1 * 0.0625f));
            int ia = max(0, (int)ceilf(-by1 * 0.0625f));
            // validity in x2/y2 at that cell (true for sane w,h)
            if ((float)(ja << 4) + bx2 < w && (float)(ia << 4) + by2 < h &&
                ja < c && ia < r) {
                int ka = (ia * c + ja) * A_NUM + a;
                if (ka < kf) kf = ka;
            }
        }
        g_kfirst = kf;
    }

    // ============ Phase 1 (single pass: chunk <= TPB) =====================
    for (int sb = base; sb < end; sb += TPB) {
        int k = sb + tid;
        int kk = min(k, end - 1);
        // kk/15 and t2/c via verified float-reciprocal (no int division)
        int t2 = (int)(((float)kk + 0.5f) * (1.0f / 15.0f));
        int a  = kk - t2 * A_NUM;
        int ii = (int)(((float)t2 + 0.5f) * inv_c);
        int jj = t2 - ii * c;
        float sx = (float)(jj << 4);
        float sy = (float)(ii << 4);

        // per-warp spatial window
        float sxlo = sx, sxhi = sx, sylo = sy, syhi = sy;
        #pragma unroll
        for (int off = 16; off; off >>= 1) {
            sxlo = fminf(sxlo, __shfl_xor_sync(FULL, sxlo, off));
            sxhi = fmaxf(sxhi, __shfl_xor_sync(FULL, sxhi, off));
            sylo = fminf(sylo, __shfl_xor_sync(FULL, sylo, off));
            syhi = fmaxf(syhi, __shfl_xor_sync(FULL, syhi, off));
        }
        float xlo = sxlo - 178.f, xhi = sxhi + 193.f;
        float ylo = sylo - 170.f, yhi = syhi + 185.f;

        float x1 = sx + c_base[a * 4 + 0];
        float y1 = sy + c_base[a * 4 + 1];
        float x2 = sx + c_base[a * 4 + 2];
        float y2 = sy + c_base[a * 4 + 3];

        bool valid  = (k < end);
        bool inside = (x1 >= 0.f) && (y1 >= 0.f) && (x2 < w) && (y2 < h);
        bool need   = inside && valid;

        if (valid)
            reinterpret_cast<float4*>(out)[k] = make_float4(x1, y1, x2, y2);

        // inside anchors are unclipped; clip is identity here
        float cx1 = fminf(fmaxf(x1, 0.f), wm1);
        float cy1 = fminf(fmaxf(y1, 0.f), hm1);
        float cx2 = fminf(fmaxf(x2, 0.f), wm1);
        float cy2 = fminf(fmaxf(y2, 0.f), hm1);
        float areaA = (cx2 - cx1 + 1.f) * (cy2 - cy1 + 1.f);

        float bi = 0.f, bd = 1.f;     // matches "all-zero row -> argmax 0"
        int   bg = -1;

        if (__any_sync(FULL, need)) {
            for (int gbs = 0; gbs < G; gbs += 32) {
                int g = gbs + lane;
                bool ok = false;
                if (g < G) {
                    float4 b = s_gt[g];
                    ok = (b.y <= yhi) && (b.w >= ylo) && (b.x <= xhi) && (b.z >= xlo);
                }
                unsigned m = __ballot_sync(FULL, ok);
                while (m) {
                    int src = __ffs(m) - 1;
                    m &= m - 1;
                    int gc = gbs + src;
                    // uniform address -> broadcast LDS (conflict-free)
                    float4 bb = s_gt[gc];
                    float  ba = s_area[gc];
                    float iw = (fminf(cx2, bb.z) - fmaxf(cx1, bb.x)) + 1.f;
                    float ih = (fminf(cy2, bb.w) - fmaxf(cy1, bb.y)) + 1.f;
                    float inter = fmaxf(iw, 0.f) * fmaxf(ih, 0.f);
                    float denom = (areaA + ba) - inter;
                    // per-anchor running max (cross-multiplication, exact)
                    if (inter * bd > bi * denom) {
                        bi = inter; bd = denom; bg = gc;
                    }
                }
            }
        }

        if (valid) {
            if (!inside) {
                tgt[k] = make_float4(0.f, 0.f, 0.f, 0.f);
                lab[k] = -1.f;
            } else {
                float mo = __fdiv_rn(bi, bd);   // exact: feeds label thresholds
                float l = -1.f;
                if (mo < 0.3f)  l = 0.f;
                if (mo >= 0.7f) l = 1.f;
                lab[k] = l;

                float4 gb = (bg >= 0) ? s_gt[bg] : gb0;
                float ew = cx2 - cx1 + 1.f, eh = cy2 - cy1 + 1.f;
                float ecx = cx1 + 0.5f * ew, ecy = cy1 + 0.5f * eh;
                float gw = gb.z - gb.x + 1.f, gh = gb.w - gb.y + 1.f;
                float gcx = gb.x + 0.5f * gw, gcy = gb.y + 0.5f * gh;
                tgt[k] = make_float4(__fdividef(gcx - ecx, ew),
                                     __fdividef(gcy - ecy, eh),
                                     __logf(__fdividef(gw, ew)),
                                     __logf(__fdividef(gh, eh)));
            }
        }
    }

    // ============ Phase 2: (gt, shape) warp-tasks, SPREAD across blocks ===
    // task = bid + nblocks*warp -> warps 0..4 of EVERY block take <=1 task,
    // so per-block added latency is one ~400-instr task, not a 16-warp pile.
    for (int task = bid + nblocks * warp; task < G * A_NUM; task += nblocks * NW) {
        int g = task / A_NUM;
        int a = task - g * A_NUM;
        float4 b = s_gt[g];
        float areaB = s_area[g];
        float bax1 = c_base[a * 4 + 0];
        float bay1 = c_base[a * 4 + 1];
        float bax2 = c_base[a * 4 + 2];
        float bay2 = c_base[a * 4 + 3];
        float areaA = (bax2 - bax1 + 1.f) * (bay2 - bay1 + 1.f);   // exact

        float sxmin = fmaxf(-bax1, b.x - bax2 - 1.f);
        float sxmax = fminf(w - bax2, b.z - bax1 + 1.f);
        float symin = fmaxf(-bay1, b.y - bay2 - 1.f);
        float symax = fminf(h - bay2, b.w - bay1 + 1.f);
        int j0 = max(0, (int)ceilf(sxmin * 0.0625f));
        int j1 = min(c - 1, (int)floorf(sxmax * 0.0625f));
        int i0 = max(0, (int)ceilf(symin * 0.0625f));
        int i1 = min(r - 1, (int)floorf(symax * 0.0625f));
        int nx = j1 - j0 + 1;
        int ny = i1 - i0 + 1;
        if (nx <= 0 || ny <= 0) continue;
        int ncell = nx * ny;
        float inv_nx = 1.0f / (float)nx;

        float bi = 0.f, bd = 1.f;
        int   bk = 0x7fffffff;

        for (int t = lane; t < ncell; t += 32) {
            int dv = (int)(((float)t + 0.5f) * inv_nx);
            int jj = j0 + (t - dv * nx);
            int ii = i0 + dv;
            float sx = (float)(jj << 4);
            float sy = (float)(ii << 4);
            float x1 = sx + bax1;
            float y1 = sy + bay1;
            float x2 = sx + bax2;
            float y2 = sy + bay2;
            bool ins = (x1 >= 0.f) && (y1 >= 0.f) && (x2 < w) && (y2 < h);
            float iw = (fminf(x2, b.z) - fmaxf(x1, b.x)) + 1.f;
            float ih = (fminf(y2, b.w) - fmaxf(y1, b.y)) + 1.f;
            float inter = fmaxf(iw, 0.f) * fmaxf(ih, 0.f);
            float denom = (areaA + areaB) - inter;
            int k = (ii * c + jj) * A_NUM + a;
            float p1 = inter * bd, p2 = bi * denom;
            // bi starts at 0 -> only inter>0 can be taken; exact tie -> min k
            if (ins && (p1 > p2 || (p1 == p2 && bi > 0.f && k < bk))) {
                bi = inter; bd = denom; bk = k;
            }
        }

        #pragma unroll
        for (int off = 16; off; off >>= 1) {
            float oi = __shfl_down_sync(FULL, bi, off);
            float od = __shfl_down_sync(FULL, bd, off);
            int   ok = __shfl_down_sync(FULL, bk, off);
            float p1 = oi * bd, p2 = bi * od;
            if (p1 > p2 || (p1 == p2 && oi > 0.f && ok < bk)) {
                bi = oi; bd = od; bk = ok;
            }
        }
        if (lane == 0 && bi > 0.f) {
            float iou = __fdiv_rn(bi, bd);       // one division per task
            unsigned long long pk =
                ((unsigned long long)__float_as_uint(iou) << 32)
                | (unsigned)(~bk);
            atomicMax(&g_pack[g], pk);           // RED; 1500 total, spread
        }
    }

    grid_barrier(nblocks);

    // ---- apply per-gt winners falling in my chunk, then count ------------
    {
        int kfirst = __ldcg(&g_kfirst);
        if (tid < G) {
            unsigned long long pk = __ldcg(&g_pack[tid]);
            int kw = (pk == 0ull) ? kfirst
                                  : (int)(~(unsigned)(pk & 0xffffffffull));
            if (kw >= base && kw < end) lab[kw] = 1.0f;
        }
    }
    __syncthreads();

    int cp = 0, cn = 0;
    for (int k = base + tid; k < end; k += TPB) {
        float l = lab[k];               // all writes here were by this block
        cp += (l == 1.f);
        cn += (l == 0.f);
    }
    #pragma unroll
    for (int off = 16; off; off >>= 1) {
        cp += __shfl_down_sync(FULL, cp, off);
        cn += __shfl_down_sync(FULL, cn, off);
    }
    if (lane == 0) { s_wp[warp] = cp; s_wn[warp] = cn; }
    __syncthreads();
    if (tid == 0) {
        int p = 0, n = 0;
        #pragma unroll
        for (int v = 0; v < NW; v++) { p += s_wp[v]; n += s_wn[v]; }
        g_bp[bid] = p; g_bn[bid] = n;
    }

    grid_barrier(nblocks);

    // ---- reset persistent state for next graph replay (post-read) --------
    if (bid == 0 && tid < G) g_pack[tid] = 0ull;

    // ---- shfl-based scan of block counts + apply subsampling -------------
    int vp = (tid < nblocks) ? __ldcg(&g_bp[tid]) : 0;
    int vn = (tid < nblocks) ? __ldcg(&g_bn[tid]) : 0;
    #pragma unroll
    for (int off = 1; off < 32; off <<= 1) {
        int tp = __shfl_up_sync(FULL, vp, off);
        int tn = __shfl_up_sync(FULL, vn, off);
        if (lane >= off) { vp += tp; vn += tn; }
    }
    if (lane == 31) { s_wp[warp] = vp; s_wn[warp] = vn; }
    __syncthreads();
    if (warp == 0 && lane < NW) {
        int wv = s_wp[lane], wn2 = s_wn[lane];
        #pragma unroll
        for (int off = 1; off < NW; off <<= 1) {
            int tp = __shfl_up_sync(0xffffu, wv, off);
            int tn = __shfl_up_sync(0xffffu, wn2, off);
            if (lane >= off) { wv += tp; wn2 += tn; }
        }
        s_wp[lane] = wv; s_wn[lane] = wn2;
    }
    __syncthreads();
    if (warp > 0) { vp += s_wp[warp - 1]; vn += s_wn[warp - 1]; }
    s_sp[tid] = vp; s_sn[tid] = vn;
    __syncthreads();

    int runP = (bid > 0) ? s_sp[bid - 1] : 0;
    int runN = (bid > 0) ? s_sn[bid - 1] : 0;
    int totP = s_sp[nblocks - 1];
    const int numBg = RPN_BATCH_C - (totP < NUM_FG ? totP : NUM_FG);
    __syncthreads();

    for (int s = base; s < end; s += TPB) {
        int k = s + tid;
        float l = (k < end) ? lab[k] : -1.f;
        int pos = (l == 1.f);
        int neg = (l == 0.f);
        unsigned ballp = __ballot_sync(FULL, pos);
        unsigned balln = __ballot_sync(FULL, neg);
        if (lane == 0) { s_wp[warp] = __popc(ballp); s_wn[warp] = __popc(balln); }
        __syncthreads();
        int wp = 0, wn = 0, totPb = 0, totNb = 0;
        #pragma unroll
        for (int v = 0; v < NW; v++) {
            int a2 = s_wp[v], b2 = s_wn[v];
            if (v < warp) { wp += a2; wn += b2; }
            totPb += a2; totNb += b2;
        }
        unsigned lm = (1u << lane) - 1u;
        int rp = runP + wp + __popc(ballp & lm) + 1;
        int rn = runN + wn + __popc(balln & lm) + 1;
        if (k < end) {
            if (pos && rp > NUM_FG) lab[k] = -1.f;
            if (neg && rn > numBg)  lab[k] = -1.f;
        }
        runP += totPb; runN += totNb;
        __syncthreads();
    }
}

// ---------------------------------------------------------------------------
extern "C" void kernel_launch(void* const* d_in, const int* in_sizes, int n_in,
                              void* d_out, int out_size) {
    const float* gt   = (const float*)d_in[0];
    const float* meta = (const float*)d_in[1];
    float* out = (float*)d_out;

    int G = in_sizes[0] / 4;
    if (G > MAX_G) G = MAX_G;
    int K  = in_sizes[2];
    int rc = K / A_NUM;
    int c  = (int)(sqrt((double)rc) + 0.5);
    int r  = rc / c;
    float inv_c = (float)(1.0 / (double)c);

    int dev = 0;
    cudaGetDevice(&dev);
    int nsm = 0;
    cudaDeviceGetAttribute(&nsm, cudaDevAttrMultiProcessorCount, dev);
    if (nsm <= 0) nsm = 148;
    int nblocks = 2 * nsm;               // 2 co-resident blocks per SM
    if (nblocks > MAX_B) nblocks = MAX_B;
    int chunk = (K + nblocks - 1) / nblocks;   // 494 for K=150000 -> 1 pass

    k_fused<<<nblocks, TPB>>>(gt, meta, out, K, r, c, G, nblocks, chunk, inv_c);
}